// round 4
// baseline (speedup 1.0000x reference)
#include <cuda_runtime.h>

// Problem constants
#define D        256
#define DD       (D * D)
#define BATCH    4096
#define T        100
#define DT_STEP  0.05f
#define NTERMS   10   // Taylor order for expm(DT*A); ||DT*A||~0.07 -> err ~1e-14

// Device scratch (static globals; no allocation anywhere)
__device__ float g_P[2][DD];      // Horner ping-pong
__device__ float g_M[T * DD];     // M[t] = expm(t*DT*A), row-major [k][d]

// ---------------------------------------------------------------------------
// init: g_P[0] = I + (DT/NTERMS)*A   (Horner seed P_{N-1}),  g_M[0] = I
// ---------------------------------------------------------------------------
__global__ void init_kernel(const float* __restrict__ A) {
    int i = blockIdx.x * blockDim.x + threadIdx.x;   // 0..DD-1
    int r = i >> 8, c = i & 255;
    float id = (r == c) ? 1.0f : 0.0f;
    g_P[0][i] = id + (DT_STEP / (float)NTERMS) * A[i];
    g_M[i] = id;
}

// ---------------------------------------------------------------------------
// 256x256x256 matmul tile body: C = alpha*(X @ Y) (+ I if addI)
// Tile: 32 rows x 64 cols per CTA, BK=16, 256 threads, 2x4 per thread.
// grid: (4 col-tiles, 8 row-tiles, batch)
// ---------------------------------------------------------------------------
__device__ __forceinline__ void mm_body(const float* __restrict__ X,
                                        const float* __restrict__ Y,
                                        float* __restrict__ C,
                                        float alpha, int addI)
{
    __shared__ float Xs[32][17];   // [row][d], padded
    __shared__ float Ys[16][64];   // [d][col], float4-aligned

    const int tid = threadIdx.x;
    const int tx = tid & 15;        // col group: cols tx*4..tx*4+3
    const int ty = tid >> 4;        // row group: rows ty*2..ty*2+1
    const int rowBase = blockIdx.y * 32;
    const int colBase = blockIdx.x * 64;

    // loader indices
    const int xr = tid >> 3;             // 0..31
    const int xd = (tid & 7) * 2;        // 0,2,..,14
    const int yd = tid >> 4;             // 0..15
    const int yc = (tid & 15) * 4;       // 0..60

    float acc[2][4];
#pragma unroll
    for (int e = 0; e < 2; ++e)
#pragma unroll
        for (int j = 0; j < 4; ++j) acc[e][j] = 0.0f;

    for (int d0 = 0; d0 < D; d0 += 16) {
        __syncthreads();
        // X tile: 32 rows x 16 d (2 elems/thread)
        float x0 = X[(rowBase + xr) * D + d0 + xd];
        float x1 = X[(rowBase + xr) * D + d0 + xd + 1];
        Xs[xr][xd]     = x0;
        Xs[xr][xd + 1] = x1;
        // Y tile: 16 d x 64 cols (float4/thread)
        float4 yv = *(const float4*)&Y[(d0 + yd) * D + colBase + yc];
        *(float4*)&Ys[yd][yc] = yv;
        __syncthreads();

#pragma unroll
        for (int kk = 0; kk < 16; ++kk) {
            float a0 = Xs[ty * 2 + 0][kk];
            float a1 = Xs[ty * 2 + 1][kk];
            float4 bv = *(const float4*)&Ys[kk][tx * 4];
            acc[0][0] += a0 * bv.x; acc[0][1] += a0 * bv.y;
            acc[0][2] += a0 * bv.z; acc[0][3] += a0 * bv.w;
            acc[1][0] += a1 * bv.x; acc[1][1] += a1 * bv.y;
            acc[1][2] += a1 * bv.z; acc[1][3] += a1 * bv.w;
        }
    }

#pragma unroll
    for (int e = 0; e < 2; ++e) {
        int gr = rowBase + ty * 2 + e;
        int gc = colBase + tx * 4;
        float4 v;
        v.x = alpha * acc[e][0]; v.y = alpha * acc[e][1];
        v.z = alpha * acc[e][2]; v.w = alpha * acc[e][3];
        if (addI) {
            if (gr == gc + 0) v.x += 1.0f;
            if (gr == gc + 1) v.y += 1.0f;
            if (gr == gc + 2) v.z += 1.0f;
            if (gr == gc + 3) v.w += 1.0f;
        }
        *(float4*)&C[gr * D + gc] = v;
    }
}

__global__ void mm_kernel(const float* __restrict__ X,
                          const float* __restrict__ Y,
                          float* __restrict__ C,
                          float alpha, int addI)
{
    mm_body(X, Y, C, alpha, addI);
}

// Parallel fill of M[10j+i] = M[10j] @ M[i]  for j=1..9, i=1..9 (81 products)
__global__ void mm_pairs_kernel(const float* __restrict__ Mbase,
                                float* __restrict__ Mout)
{
    int p = blockIdx.z;
    int j = p / 9 + 1;
    int i = p % 9 + 1;
    mm_body(Mbase + (size_t)(10 * j) * DD,
            Mbase + (size_t)i * DD,
            Mout + (size_t)(10 * j + i) * DD,
            1.0f, 0);
}

// ---------------------------------------------------------------------------
// Main trajectory GEMM: out[b,t,k] = sum_d X0[b,d] * M[t,k,d]
// CTA: 64 b-rows x 64 k-cols, one t. 256 threads, 4x4 per thread, BK=16.
// grid: (BATCH/64, D/64, T) = (64, 4, 100)
// ---------------------------------------------------------------------------
__global__ void __launch_bounds__(256)
traj_kernel(const float* __restrict__ X0,
            const float* __restrict__ M,
            float* __restrict__ out)
{
    const int t = blockIdx.z;
    const int bBase = blockIdx.x * 64;
    const int kBase = blockIdx.y * 64;
    const float* __restrict__ Mt = M + (size_t)t * DD;

    __shared__ float Xs[16][64];   // [d][b]
    __shared__ float Ms[16][64];   // [d][k]

    const int tid = threadIdx.x;
    const int tx = tid & 15;         // k cols tx*4..+3
    const int ty = tid >> 4;         // b rows ty*4..+3
    const int lrow = tid >> 2;       // 0..63
    const int lq = (tid & 3) << 2;   // 0,4,8,12 (d offset)

    const float* xPtr = X0 + (size_t)(bBase + lrow) * D + lq;
    const float* mPtr = Mt + (size_t)(kBase + lrow) * D + lq;

    float acc[4][4];
#pragma unroll
    for (int i = 0; i < 4; ++i)
#pragma unroll
        for (int j = 0; j < 4; ++j) acc[i][j] = 0.0f;

    // prefetch chunk 0
    float4 xv = *(const float4*)(xPtr);
    float4 mv = *(const float4*)(mPtr);

    for (int d0 = 0; d0 < D; d0 += 16) {
        __syncthreads();
        Xs[lq + 0][lrow] = xv.x; Xs[lq + 1][lrow] = xv.y;
        Xs[lq + 2][lrow] = xv.z; Xs[lq + 3][lrow] = xv.w;
        Ms[lq + 0][lrow] = mv.x; Ms[lq + 1][lrow] = mv.y;
        Ms[lq + 2][lrow] = mv.z; Ms[lq + 3][lrow] = mv.w;
        __syncthreads();

        if (d0 + 16 < D) {  // prefetch next chunk under compute
            xv = *(const float4*)(xPtr + d0 + 16);
            mv = *(const float4*)(mPtr + d0 + 16);
        }

#pragma unroll
        for (int kk = 0; kk < 16; ++kk) {
            float4 av = *(const float4*)&Xs[kk][ty * 4];   // broadcast-heavy
            float4 bv = *(const float4*)&Ms[kk][tx * 4];   // phase-clean
            acc[0][0] += av.x * bv.x; acc[0][1] += av.x * bv.y;
            acc[0][2] += av.x * bv.z; acc[0][3] += av.x * bv.w;
            acc[1][0] += av.y * bv.x; acc[1][1] += av.y * bv.y;
            acc[1][2] += av.y * bv.z; acc[1][3] += av.y * bv.w;
            acc[2][0] += av.z * bv.x; acc[2][1] += av.z * bv.y;
            acc[2][2] += av.z * bv.z; acc[2][3] += av.z * bv.w;
            acc[3][0] += av.w * bv.x; acc[3][1] += av.w * bv.y;
            acc[3][2] += av.w * bv.z; acc[3][3] += av.w * bv.w;
        }
    }

    // out[b, t, k]: 4 coalesced float4 rows per thread
#pragma unroll
    for (int r = 0; r < 4; ++r) {
        size_t o = ((size_t)(bBase + ty * 4 + r) * T + t) * D + kBase + tx * 4;
        float4 v;
        v.x = acc[r][0]; v.y = acc[r][1]; v.z = acc[r][2]; v.w = acc[r][3];
        *(float4*)(out + o) = v;
    }
}

// ---------------------------------------------------------------------------
// kernel_launch: pure kernel launches (graph-capturable, allocation-free)
// ---------------------------------------------------------------------------
extern "C" void kernel_launch(void* const* d_in, const int* in_sizes, int n_in,
                              void* d_out, int out_size)
{
    const float* X0 = (const float*)d_in[0];   // [BATCH, D]
    const float* A  = (const float*)d_in[1];   // [D, D]
    if (n_in >= 2 && in_sizes[0] == DD && in_sizes[1] == BATCH * D) {
        // defensive: metadata order swapped
        const float* tmp = X0; X0 = A; A = tmp;
    }
    float* out = (float*)d_out;

    float* Mbase = nullptr;
    float* Pbase = nullptr;
    cudaGetSymbolAddress((void**)&Mbase, g_M);
    cudaGetSymbolAddress((void**)&Pbase, g_P);

    const dim3 mmGrid(4, 8, 1);   // 64-col x 32-row tiles over 256x256

    // 1) seed: g_P[0] = I + (DT/N)A ; g_M[0] = I
    init_kernel<<<DD / 256, 256>>>(A);

    // 2) Horner for E = expm(DT*A):  P <- I + (DT/k) * (A @ P),  k = N-1..1
    //    final result (k==1) lands in M[1].
    float* Pc = Pbase;
    float* Pn = Pbase + DD;
    for (int k = NTERMS - 1; k >= 1; --k) {
        float* dst = (k == 1) ? (Mbase + DD) : Pn;
        mm_kernel<<<mmGrid, 256>>>(A, Pc, dst, DT_STEP / (float)k, 1);
        float* tswap = Pc; Pc = Pn; Pn = tswap;
    }

    // 3) S chain: M[i] = M[i-1] @ M[1], i = 2..10  (M[10] = E^10)
    for (int i = 2; i <= 10; ++i)
        mm_kernel<<<mmGrid, 256>>>(Mbase + (size_t)(i - 1) * DD,
                                   Mbase + DD,
                                   Mbase + (size_t)i * DD, 1.0f, 0);

    // 4) P chain: M[10j] = M[10(j-1)] @ M[10], j = 2..9
    for (int j = 2; j <= 9; ++j)
        mm_kernel<<<mmGrid, 256>>>(Mbase + (size_t)(10 * (j - 1)) * DD,
                                   Mbase + (size_t)(10) * DD,
                                   Mbase + (size_t)(10 * j) * DD, 1.0f, 0);

    // 5) All cross terms in parallel: M[10j+i] = M[10j] @ M[i], j,i in 1..9
    mm_pairs_kernel<<<dim3(4, 8, 81), 256>>>(Mbase, Mbase);

    // 6) Main einsum: out[b,t,k] = X0[b,:] . M[t,k,:]
    traj_kernel<<<dim3(BATCH / 64, D / 64, T), 256>>>(X0, Mbase, out);

    (void)n_in; (void)out_size;
}

// round 5
// speedup vs baseline: 1.1245x; 1.1245x over previous
#include <cuda_runtime.h>

// Problem constants
#define D        256
#define DD       65536
#define BATCH    4096
#define T        100
#define DT_STEP  0.05f

// Device scratch (static globals; no allocation anywhere)
__device__ float g_W[8ull * DD];          // A powers: W[k] = A^k, k=1..7 (slot 0 unused)
__device__ float g_M[(size_t)T * DD];     // M[t] = expm(t*DT*A), row-major [k][d]

// ---------------------------------------------------------------------------
// f32x2 packed-FMA helpers (sm_100+ PTX)
// ---------------------------------------------------------------------------
typedef unsigned long long u64t;

__device__ __forceinline__ u64t pack_dup(float v) {
    u64t r;
    asm("mov.b64 %0, {%1, %1};" : "=l"(r) : "f"(v));
    return r;
}
__device__ __forceinline__ void fma2(u64t& d, u64t a, u64t b) {
    asm("fma.rn.f32x2 %0, %1, %2, %0;" : "+l"(d) : "l"(a), "l"(b));
}

// ---------------------------------------------------------------------------
// init: g_M[0] = I, g_W[1] = A
// ---------------------------------------------------------------------------
__global__ void init_kernel(const float* __restrict__ A) {
    int i = blockIdx.x * blockDim.x + threadIdx.x;     // 0..DD-1
    int r = i >> 8, c = i & 255;
    g_M[i] = (r == c) ? 1.0f : 0.0f;
    g_W[DD + i] = A[i];
}

// ---------------------------------------------------------------------------
// esum: g_M[1] = E = I + sum_{k=1..7} (DT^k / k!) * A^k
// ---------------------------------------------------------------------------
__global__ void esum_kernel() {
    int i = blockIdx.x * blockDim.x + threadIdx.x;
    int r = i >> 8, c = i & 255;
    float acc = (r == c) ? 1.0f : 0.0f;
    acc += 5.0000000e-02f * g_W[1 * DD + i];
    acc += 1.2500000e-03f * g_W[2 * DD + i];
    acc += 2.0833333e-05f * g_W[3 * DD + i];
    acc += 2.6041667e-07f * g_W[4 * DD + i];
    acc += 2.6041667e-09f * g_W[5 * DD + i];
    acc += 2.1701389e-11f * g_W[6 * DD + i];
    acc += 1.5500992e-13f * g_W[7 * DD + i];
    g_M[DD + i] = acc;
}

// ---------------------------------------------------------------------------
// Batched small 256x256x256 matmul: C[z] = X @ Y[z]
//   X fixed, Y[z] = Y0 + z*DD, C[z] = C0 + z*DD.
// Tile 32x32, BK=32, 256 threads, 2x2 per thread. grid (8, 8, zcnt).
// Register prefetch across the barrier to hide L2 latency (these launches
// were latency-bound at 18.4us / 12.8% occ before).
// ---------------------------------------------------------------------------
__global__ void __launch_bounds__(256)
mm_batch_kernel(const float* __restrict__ X,
                const float* __restrict__ Y0,
                float* __restrict__ C0)
{
    const float* __restrict__ Y = Y0 + (size_t)blockIdx.z * DD;
    float* __restrict__ C = C0 + (size_t)blockIdx.z * DD;
    const int rowBase = blockIdx.y * 32;
    const int colBase = blockIdx.x * 32;

    __shared__ float Xs[32][34];   // [k][r], pad keeps float2 reads 8B-aligned
    __shared__ float Ys[32][32];   // [k][c]

    const int tid = threadIdx.x;
    const int lrow = tid >> 3;          // 0..31
    const int lq   = (tid & 7) * 4;     // 0,4,...,28

    const int tx = tid & 15;            // cols tx*2..+1
    const int ty = tid >> 4;            // rows ty*2..+1

    const float* xPtr = X + (size_t)(rowBase + lrow) * D + lq;     // advance along k
    const float* yPtr = Y + (size_t)lrow * D + colBase + lq;       // advance along k rows

    float4 xv = *(const float4*)xPtr;
    float4 yv = *(const float4*)yPtr;

    float a00 = 0.f, a01 = 0.f, a10 = 0.f, a11 = 0.f;

    for (int d0 = 0; d0 < D; d0 += 32) {
        __syncthreads();
        Xs[lq + 0][lrow] = xv.x; Xs[lq + 1][lrow] = xv.y;
        Xs[lq + 2][lrow] = xv.z; Xs[lq + 3][lrow] = xv.w;
        *(float4*)&Ys[lrow][lq] = yv;
        __syncthreads();

        if (d0 + 32 < D) {  // prefetch next chunk under compute
            xv = *(const float4*)(xPtr + d0 + 32);
            yv = *(const float4*)(yPtr + (size_t)(d0 + 32) * D);
        }

#pragma unroll
        for (int kk = 0; kk < 32; ++kk) {
            float2 a = *(const float2*)&Xs[kk][ty * 2];
            float2 b = *(const float2*)&Ys[kk][tx * 2];
            a00 += a.x * b.x; a01 += a.x * b.y;
            a10 += a.y * b.x; a11 += a.y * b.y;
        }
    }

    int gr = rowBase + ty * 2;
    int gc = colBase + tx * 2;
    float2 v0; v0.x = a00; v0.y = a01;
    float2 v1; v1.x = a10; v1.y = a11;
    *(float2*)&C[(size_t)gr * D + gc] = v0;
    *(float2*)&C[(size_t)(gr + 1) * D + gc] = v1;
}

// ---------------------------------------------------------------------------
// Main trajectory GEMM: out[b,t,k] = sum_d X0[b,d] * M[t,k,d]
// CTA: 64 b-rows x 64 k-cols, one t. 256 threads, 4x4 per thread, BK=16.
// Inner loop uses packed fma.rn.f32x2: 8 FFMA2 + 4 packs + 2 LDS.128 per kk
// -> fma-pipe cycles per kk halved vs scalar FFMA.
// grid: (BATCH/64, D/64, T) = (64, 4, 100)
// ---------------------------------------------------------------------------
__global__ void __launch_bounds__(256)
traj_kernel(const float* __restrict__ X0,
            const float* __restrict__ M,
            float* __restrict__ out)
{
    const int t = blockIdx.z;
    const int bBase = blockIdx.x * 64;
    const int kBase = blockIdx.y * 64;
    const float* __restrict__ Mt = M + (size_t)t * DD;

    __shared__ float Xs[16][64];   // [d][b]
    __shared__ float Ms[16][64];   // [d][k]

    const int tid = threadIdx.x;
    const int tx = tid & 15;         // k cols tx*4..+3
    const int ty = tid >> 4;         // b rows ty*4..+3
    const int lrow = tid >> 2;       // 0..63
    const int lq = (tid & 3) << 2;   // 0,4,8,12 (d offset)

    const float* xPtr = X0 + (size_t)(bBase + lrow) * D + lq;
    const float* mPtr = Mt + (size_t)(kBase + lrow) * D + lq;

    u64t acc[4][2];
#pragma unroll
    for (int i = 0; i < 4; ++i) { acc[i][0] = 0ull; acc[i][1] = 0ull; }

    // prefetch chunk 0
    float4 xv = *(const float4*)(xPtr);
    float4 mv = *(const float4*)(mPtr);

    for (int d0 = 0; d0 < D; d0 += 16) {
        __syncthreads();
        Xs[lq + 0][lrow] = xv.x; Xs[lq + 1][lrow] = xv.y;
        Xs[lq + 2][lrow] = xv.z; Xs[lq + 3][lrow] = xv.w;
        Ms[lq + 0][lrow] = mv.x; Ms[lq + 1][lrow] = mv.y;
        Ms[lq + 2][lrow] = mv.z; Ms[lq + 3][lrow] = mv.w;
        __syncthreads();

        if (d0 + 16 < D) {  // prefetch next chunk under compute
            xv = *(const float4*)(xPtr + d0 + 16);
            mv = *(const float4*)(mPtr + d0 + 16);
        }

#pragma unroll
        for (int kk = 0; kk < 16; ++kk) {
            float4 av = *(const float4*)&Xs[kk][ty * 4];          // broadcast
            ulonglong2 bp = *(const ulonglong2*)&Ms[kk][tx * 4];  // 2 packed f32x2
            u64t a0 = pack_dup(av.x);
            u64t a1 = pack_dup(av.y);
            u64t a2 = pack_dup(av.z);
            u64t a3 = pack_dup(av.w);
            fma2(acc[0][0], a0, bp.x); fma2(acc[0][1], a0, bp.y);
            fma2(acc[1][0], a1, bp.x); fma2(acc[1][1], a1, bp.y);
            fma2(acc[2][0], a2, bp.x); fma2(acc[2][1], a2, bp.y);
            fma2(acc[3][0], a3, bp.x); fma2(acc[3][1], a3, bp.y);
        }
    }

    // out[b, t, k]: 4 coalesced 16B rows per thread; packed accs store directly
#pragma unroll
    for (int r = 0; r < 4; ++r) {
        size_t o = ((size_t)(bBase + ty * 4 + r) * T + t) * D + kBase + tx * 4;
        ulonglong2 v;
        v.x = acc[r][0];
        v.y = acc[r][1];
        *(ulonglong2*)(out + o) = v;
    }
}

// ---------------------------------------------------------------------------
// kernel_launch: pure kernel launches (graph-capturable, allocation-free)
// ---------------------------------------------------------------------------
extern "C" void kernel_launch(void* const* d_in, const int* in_sizes, int n_in,
                              void* d_out, int out_size)
{
    const float* X0 = (const float*)d_in[0];   // [BATCH, D]
    const float* A  = (const float*)d_in[1];   // [D, D]
    if (n_in >= 2 && in_sizes[0] == DD && in_sizes[1] == BATCH * D) {
        const float* tmp = X0; X0 = A; A = tmp;  // defensive: metadata order swapped
    }
    float* out = (float*)d_out;

    float* Mb = nullptr;
    float* Wb = nullptr;
    cudaGetSymbolAddress((void**)&Mb, g_M);
    cudaGetSymbolAddress((void**)&Wb, g_W);

#define WP(k) (Wb + (size_t)(k) * DD)
#define MP(k) (Mb + (size_t)(k) * DD)

    // 1) seed: M[0] = I, W[1] = A
    init_kernel<<<DD / 256, 256>>>(A);

    // 2) A powers (serial depth 3): A^2; {A^3,A^4}; {A^5..A^7}
    mm_batch_kernel<<<dim3(8, 8, 1), 256>>>(WP(2 - 1), WP(1), WP(2));  // X=A
    mm_batch_kernel<<<dim3(8, 8, 2), 256>>>(WP(2), WP(1), WP(3));     // A2*{A1,A2}
    mm_batch_kernel<<<dim3(8, 8, 3), 256>>>(WP(4), WP(1), WP(5));     // A4*{A1..A3}

    // 3) E = I + sum c_k A^k  -> M[1]
    esum_kernel<<<DD / 256, 256>>>();

    // 4) Binary-doubling table fill: M[n+i] = M[n]*M[i], i=1..min(n, 99-n)
    mm_batch_kernel<<<dim3(8, 8, 1),  256>>>(MP(1),  MP(1), MP(2));
    mm_batch_kernel<<<dim3(8, 8, 2),  256>>>(MP(2),  MP(1), MP(3));
    mm_batch_kernel<<<dim3(8, 8, 4),  256>>>(MP(4),  MP(1), MP(5));
    mm_batch_kernel<<<dim3(8, 8, 8),  256>>>(MP(8),  MP(1), MP(9));
    mm_batch_kernel<<<dim3(8, 8, 16), 256>>>(MP(16), MP(1), MP(17));
    mm_batch_kernel<<<dim3(8, 8, 32), 256>>>(MP(32), MP(1), MP(33));
    mm_batch_kernel<<<dim3(8, 8, 35), 256>>>(MP(64), MP(1), MP(65));

    // 5) Main einsum: out[b,t,k] = X0[b,:] . M[t,k,:]
    traj_kernel<<<dim3(BATCH / 64, D / 64, T), 256>>>(X0, Mb, out);

#undef WP
#undef MP
    (void)n_in; (void)out_size;
}

// round 7
// speedup vs baseline: 3.9594x; 3.5210x over previous
#include <cuda_runtime.h>
#include <cuda_bf16.h>

// Problem constants
#define D        256
#define DD       65536
#define BATCH    4096
#define T        100
#define DT_STEP  0.05f
#define NPOW     14          // B-powers kept (k=1..14)

typedef unsigned int u32;

// ---------------------------------------------------------------------------
// Device scratch (static globals; no allocation anywhere)
// ---------------------------------------------------------------------------
__device__ float          g_W[15ull * DD];            // B^k, k=1..14 (slot 0 unused)
__device__ __nv_bfloat16  g_Mhi[(size_t)T * DD];      // hi split of M[t] = expm(t*dt*A)
__device__ __nv_bfloat16  g_Mlo[(size_t)T * DD];      // lo split
__device__ __nv_bfloat16  g_Xhi[(size_t)BATCH * D];
__device__ __nv_bfloat16  g_Xlo[(size_t)BATCH * D];

// ---------------------------------------------------------------------------
// PTX helpers (baseline ISA only — no sm_103a-accelerated features)
// ---------------------------------------------------------------------------
__device__ __forceinline__ u32 smem_u32(const void* p) {
    u32 a;
    asm("{ .reg .u64 t; cvta.to.shared.u64 t, %1; cvt.u32.u64 %0, t; }" : "=r"(a) : "l"(p));
    return a;
}
__device__ __forceinline__ void cpa16(u32 dst, const void* src) {
    asm volatile("cp.async.cg.shared.global [%0], [%1], 16;" :: "r"(dst), "l"(src) : "memory");
}
__device__ __forceinline__ void cpa_commit() { asm volatile("cp.async.commit_group;" ::: "memory"); }
template <int N>
__device__ __forceinline__ void cpa_wait() {
    asm volatile("cp.async.wait_group %0;" :: "n"(N) : "memory");
}
__device__ __forceinline__ void ldm4(u32* r, u32 a) {
    asm volatile("ldmatrix.sync.aligned.m8n8.x4.shared.b16 {%0,%1,%2,%3}, [%4];"
                 : "=r"(r[0]), "=r"(r[1]), "=r"(r[2]), "=r"(r[3]) : "r"(a));
}
__device__ __forceinline__ void mma16816(float* c, const u32* a, u32 b0, u32 b1) {
    asm volatile("mma.sync.aligned.m16n8k16.row.col.f32.bf16.bf16.f32 "
                 "{%0,%1,%2,%3}, {%4,%5,%6,%7}, {%8,%9}, {%0,%1,%2,%3};"
                 : "+f"(c[0]), "+f"(c[1]), "+f"(c[2]), "+f"(c[3])
                 : "r"(a[0]), "r"(a[1]), "r"(a[2]), "r"(a[3]), "r"(b0), "r"(b1));
}

#define SWZ(o) ((o) ^ (((o) >> 3) & 0x70))

// ---------------------------------------------------------------------------
// initB: g_W[1] = B = A + I
// ---------------------------------------------------------------------------
__global__ void initB_kernel(const float* __restrict__ A) {
    int i = blockIdx.x * blockDim.x + threadIdx.x;   // 0..DD-1
    int r = i >> 8, c = i & 255;
    g_W[DD + i] = A[i] + ((r == c) ? 1.0f : 0.0f);
}

// ---------------------------------------------------------------------------
// Batched small 256x256x256 fp32 matmul: C[z] = X @ Y[z]  (proven in R5)
// ---------------------------------------------------------------------------
__global__ void __launch_bounds__(256)
mm_batch_kernel(const float* __restrict__ X,
                const float* __restrict__ Y0,
                float* __restrict__ C0)
{
    const float* __restrict__ Y = Y0 + (size_t)blockIdx.z * DD;
    float* __restrict__ C = C0 + (size_t)blockIdx.z * DD;
    const int rowBase = blockIdx.y * 32;
    const int colBase = blockIdx.x * 32;

    __shared__ float Xs[32][34];
    __shared__ float Ys[32][32];

    const int tid = threadIdx.x;
    const int lrow = tid >> 3;
    const int lq   = (tid & 7) * 4;
    const int tx = tid & 15;
    const int ty = tid >> 4;

    const float* xPtr = X + (size_t)(rowBase + lrow) * D + lq;
    const float* yPtr = Y + (size_t)lrow * D + colBase + lq;

    float4 xv = *(const float4*)xPtr;
    float4 yv = *(const float4*)yPtr;

    float a00 = 0.f, a01 = 0.f, a10 = 0.f, a11 = 0.f;

    for (int d0 = 0; d0 < D; d0 += 32) {
        __syncthreads();
        Xs[lq + 0][lrow] = xv.x; Xs[lq + 1][lrow] = xv.y;
        Xs[lq + 2][lrow] = xv.z; Xs[lq + 3][lrow] = xv.w;
        *(float4*)&Ys[lrow][lq] = yv;
        __syncthreads();

        if (d0 + 32 < D) {
            xv = *(const float4*)(xPtr + d0 + 32);
            yv = *(const float4*)(yPtr + (size_t)(d0 + 32) * D);
        }

#pragma unroll
        for (int kk = 0; kk < 32; ++kk) {
            float2 a = *(const float2*)&Xs[kk][ty * 2];
            float2 b = *(const float2*)&Ys[kk][tx * 2];
            a00 += a.x * b.x; a01 += a.x * b.y;
            a10 += a.y * b.x; a11 += a.y * b.y;
        }
    }

    int gr = rowBase + ty * 2;
    int gc = colBase + tx * 2;
    float2 v0; v0.x = a00; v0.y = a01;
    float2 v1; v1.x = a10; v1.y = a11;
    *(float2*)&C[(size_t)gr * D + gc] = v0;
    *(float2*)&C[(size_t)(gr + 1) * D + gc] = v1;
}

// ---------------------------------------------------------------------------
// gen_split: M[t][i] = e^{-t*dt} * sum_{k=0..14} (t*dt)^k/k! * B^k[i],
// written pre-split into bf16 hi/lo. One CTA owns a 512-elem slice for all t.
// ---------------------------------------------------------------------------
__global__ void __launch_bounds__(256)
gen_split_kernel()
{
    __shared__ float sm[NPOW][512];
    const int base = blockIdx.x * 512;
    const int tid = threadIdx.x;

    for (int v = tid; v < NPOW * 512; v += 256) {
        int k = v >> 9, j = v & 511;
        sm[k][j] = g_W[(size_t)(k + 1) * DD + base + j];
    }
    __syncthreads();

    const int i0 = base + tid;
    const int i1 = base + tid + 256;
    const float id0 = ((i0 >> 8) == (i0 & 255)) ? 1.0f : 0.0f;
    const float id1 = ((i1 >> 8) == (i1 & 255)) ? 1.0f : 0.0f;

    for (int t = 0; t < T; ++t) {
        float s = DT_STEP * (float)t;
        float c = expf(-s);
        float a0 = c * id0, a1 = c * id1;
        float ck = c;
#pragma unroll
        for (int k = 1; k <= NPOW; ++k) {
            ck *= s / (float)k;
            a0 += ck * sm[k - 1][tid];
            a1 += ck * sm[k - 1][tid + 256];
        }
        size_t o0 = (size_t)t * DD + i0;
        size_t o1 = (size_t)t * DD + i1;
        __nv_bfloat16 h0 = __float2bfloat16(a0);
        __nv_bfloat16 h1 = __float2bfloat16(a1);
        g_Mhi[o0] = h0; g_Mlo[o0] = __float2bfloat16(a0 - __bfloat162float(h0));
        g_Mhi[o1] = h1; g_Mlo[o1] = __float2bfloat16(a1 - __bfloat162float(h1));
    }
}

// ---------------------------------------------------------------------------
// split_x: X0 -> bf16 hi/lo. 1M elems, 4/thread.
// ---------------------------------------------------------------------------
__global__ void split_x_kernel(const float* __restrict__ X0) {
    int i = (blockIdx.x * 256 + threadIdx.x) * 4;
    float4 v = *(const float4*)(X0 + i);
    float xs[4] = {v.x, v.y, v.z, v.w};
#pragma unroll
    for (int j = 0; j < 4; ++j) {
        __nv_bfloat16 h = __float2bfloat16(xs[j]);
        g_Xhi[i + j] = h;
        g_Xlo[i + j] = __float2bfloat16(xs[j] - __bfloat162float(h));
    }
}

// ---------------------------------------------------------------------------
// traj_hmma: out[b,t,k] = sum_d X0[b,d]*M[t,k,d] via mma.sync bf16 split-3.
// CTA tile: 128 (batch) x 128 (k-cols) x K=256. 8 warps, warp tile 64x32.
// cp.async double-buffered K chunks of 64 (128B swizzled rows).
// grid (32, 2, 100), 256 threads.
// ---------------------------------------------------------------------------
#define TB_XHI 0
#define TB_XLO 16384
#define TB_MHI 32768
#define TB_MLO 49152
#define BUFSZ  65536
#define SMEM_TRAJ (2 * BUFSZ)   // 128 KB dynamic

__global__ void __launch_bounds__(256)
traj_hmma_kernel(float* __restrict__ out)
{
    extern __shared__ char dsm[];
    const u32 sb = smem_u32(dsm);
    const int tid = threadIdx.x;
    const int lane = tid & 31;
    const int wid = tid >> 5;
    const int t = blockIdx.z;
    const int bBase = blockIdx.x * 128;
    const int nBase = blockIdx.y * 128;

    const __nv_bfloat16* __restrict__ xh = g_Xhi + (size_t)bBase * D;
    const __nv_bfloat16* __restrict__ xl = g_Xlo + (size_t)bBase * D;
    const __nv_bfloat16* __restrict__ mh = g_Mhi + (size_t)t * DD + (size_t)nBase * D;
    const __nv_bfloat16* __restrict__ ml = g_Mlo + (size_t)t * DD + (size_t)nBase * D;

    // warp tiling: wm in {0,64}, wn in {0,32,64,96}
    const int wm = (wid & 1) * 64;
    const int wn = (wid >> 1) * 32;
    // ldmatrix per-lane address components
    const int aRow  = wm + (lane & 15);               // A: rows m..m+15
    const u32 aColB = (u32)(((lane >> 4) * 8) * 2);   // k half select (bytes)
    const int bRow  = wn + ((lane >> 4) << 3) + (lane & 7);  // B: n rows
    const u32 bColB = (u32)((((lane >> 3) & 1) * 8) * 2);

    float acc[4][4][4];
#pragma unroll
    for (int mi = 0; mi < 4; ++mi)
#pragma unroll
        for (int nf = 0; nf < 4; ++nf)
#pragma unroll
            for (int r = 0; r < 4; ++r) acc[mi][nf][r] = 0.0f;

    // ---- chunk loader: 4 tiles x 1024 x 16B, swizzled 128B rows ----
    auto load_chunk = [&](int buf, int cd) {
        u32 sbuf = sb + (u32)buf * BUFSZ;
#pragma unroll
        for (int it = 0; it < 4; ++it) {
            int v = tid + it * 256;
            int r = v >> 3, j = v & 7;
            u32 off = SWZ((u32)(r * 128 + j * 16));
            size_t g = (size_t)r * D + cd + j * 8;
            cpa16(sbuf + TB_XHI + off, xh + g);
            cpa16(sbuf + TB_XLO + off, xl + g);
            cpa16(sbuf + TB_MHI + off, mh + g);
            cpa16(sbuf + TB_MLO + off, ml + g);
        }
        cpa_commit();
    };

    load_chunk(0, 0);

    for (int c = 0; c < 4; ++c) {
        if (c < 3) { load_chunk((c + 1) & 1, (c + 1) * 64); cpa_wait<1>(); }
        else       { cpa_wait<0>(); }
        __syncthreads();

        const u32 sbuf = sb + (u32)(c & 1) * BUFSZ;

#pragma unroll
        for (int k16 = 0; k16 < 4; ++k16) {
            const u32 kb = (u32)(k16 * 32);   // byte offset of this k16 within row

            // B fragments (Mhi, Mlo): two x4 each -> frags nf=0..3
            u32 bh[8], bl[8];
            {
                u32 o0 = SWZ((u32)(bRow * 128) + kb + bColB);
                u32 o1 = SWZ((u32)((bRow + 16) * 128) + kb + bColB);
                ldm4(bh,     sbuf + TB_MHI + o0);
                ldm4(bh + 4, sbuf + TB_MHI + o1);
                ldm4(bl,     sbuf + TB_MLO + o0);
                ldm4(bl + 4, sbuf + TB_MLO + o1);
            }

            // A hi fragments
            u32 af[4][4];
#pragma unroll
            for (int mi = 0; mi < 4; ++mi) {
                u32 oa = SWZ((u32)((aRow + mi * 16) * 128) + kb + aColB);
                ldm4(af[mi], sbuf + TB_XHI + oa);
            }
            // hi*hi + hi*lo
#pragma unroll
            for (int mi = 0; mi < 4; ++mi)
#pragma unroll
                for (int nf = 0; nf < 4; ++nf) {
                    mma16816(acc[mi][nf], af[mi], bh[nf * 2], bh[nf * 2 + 1]);
                    mma16816(acc[mi][nf], af[mi], bl[nf * 2], bl[nf * 2 + 1]);
                }
            // A lo fragments (overwrite) ; lo*hi
#pragma unroll
            for (int mi = 0; mi < 4; ++mi) {
                u32 oa = SWZ((u32)((aRow + mi * 16) * 128) + kb + aColB);
                ldm4(af[mi], sbuf + TB_XLO + oa);
            }
#pragma unroll
            for (int mi = 0; mi < 4; ++mi)
#pragma unroll
                for (int nf = 0; nf < 4; ++nf)
                    mma16816(acc[mi][nf], af[mi], bh[nf * 2], bh[nf * 2 + 1]);
        }
        __syncthreads();
    }

    // ---- epilogue: out[b, t, k], float2 stores ----
    const int gr = lane >> 2;
    const int gc = (lane & 3) * 2;
#pragma unroll
    for (int mi = 0; mi < 4; ++mi) {
#pragma unroll
        for (int nf = 0; nf < 4; ++nf) {
            int r0 = bBase + wm + mi * 16 + gr;
            int c0 = nBase + wn + nf * 8 + gc;
            float2 v0; v0.x = acc[mi][nf][0]; v0.y = acc[mi][nf][1];
            float2 v1; v1.x = acc[mi][nf][2]; v1.y = acc[mi][nf][3];
            *(float2*)(out + ((size_t)r0 * T + t) * D + c0) = v0;
            *(float2*)(out + ((size_t)(r0 + 8) * T + t) * D + c0) = v1;
        }
    }
}

// ---------------------------------------------------------------------------
// kernel_launch: pure kernel launches (graph-capturable, allocation-free)
// ---------------------------------------------------------------------------
extern "C" void kernel_launch(void* const* d_in, const int* in_sizes, int n_in,
                              void* d_out, int out_size)
{
    const float* X0 = (const float*)d_in[0];   // [BATCH, D]
    const float* A  = (const float*)d_in[1];   // [D, D]
    if (n_in >= 2 && in_sizes[0] == DD && in_sizes[1] == BATCH * D) {
        const float* tmp = X0; X0 = A; A = tmp;  // defensive: metadata order swapped
    }
    float* out = (float*)d_out;

    float* Wb = nullptr;
    cudaGetSymbolAddress((void**)&Wb, g_W);
#define WP(k) (Wb + (size_t)(k) * DD)

    cudaFuncSetAttribute(traj_hmma_kernel,
                         cudaFuncAttributeMaxDynamicSharedMemorySize, SMEM_TRAJ);

    // 1) B = A + I
    initB_kernel<<<DD / 256, 256>>>(A);

    // 2) B powers, serial depth 4: B2; {B3,B4}; {B5..B8}; {B9..B14}
    mm_batch_kernel<<<dim3(8, 8, 1), 256>>>(WP(1), WP(1), WP(2));
    mm_batch_kernel<<<dim3(8, 8, 2), 256>>>(WP(2), WP(1), WP(3));
    mm_batch_kernel<<<dim3(8, 8, 4), 256>>>(WP(4), WP(1), WP(5));
    mm_batch_kernel<<<dim3(8, 8, 6), 256>>>(WP(8), WP(1), WP(9));

    // 3) All 100 M[t] from the series, pre-split to bf16 hi/lo
    gen_split_kernel<<<128, 256>>>();

    // 4) X0 hi/lo split (independent; cheap)
    split_x_kernel<<<(BATCH * D) / (256 * 4), 256>>>(X0);

    // 5) Main einsum on tensor cores (mma.sync bf16, 3-term split)
    traj_hmma_kernel<<<dim3(BATCH / 128, D / 128, T), 256, SMEM_TRAJ>>>(out);

#undef WP
    (void)n_in; (void)out_size;
}